// round 4
// baseline (speedup 1.0000x reference)
#include <cuda_runtime.h>
#include <cuda_fp16.h>

// DiffeomorphicTransform: scaling-and-squaring integration.
// flow = v/2^7 ; 7x: flow += trilerp(flow, pos + flow*scale), border clamp.
// Identity grid folded: ix = x + flow_x * (rf*(W-1)/2), clamped.
//
// Storage:
//   fp32 SoA (3 planes, 31.5MB) -> accumulator chain, updated IN PLACE
//       (only ever read at self index, so no ping-pong needed)
//   fp16 PAIR buffers (2 x 42MB, ping-pong) -> gathers: entry i = 16B =
//       voxels (i, i+1) as 6 halves; one aligned LDG.128 = both x-corners.
// Resident set 115.5MB < 126MB L2.

#define DD 128
#define HH 160
#define WW 128
#define NV (DD * HH * WW)   // 2,621,440

__device__ float g_fx[NV];
__device__ float g_fy[NV];
__device__ float g_fz[NV];
__device__ uint4 g_p16A[NV];
__device__ uint4 g_p16B[NV];

__device__ __forceinline__ float lerpf(float a, float b, float t) {
    return fmaf(t, b - a, a);
}

__device__ __forceinline__ __half2 u2h2(unsigned int u) {
    return *reinterpret_cast<const __half2*>(&u);
}

// One LDG.128 -> both x-corners of one row; lerp in x, return float3.
__device__ __forceinline__ float3 pair_lerp(const uint4* __restrict__ buf,
                                            int idx, float fx) {
    uint4 v = __ldg(buf + idx);
    float2 xy0 = __half22float2(u2h2(v.x));
    float2 zw0 = __half22float2(u2h2(v.y));
    float2 xy1 = __half22float2(u2h2(v.z));
    float2 zw1 = __half22float2(u2h2(v.w));
    float3 r;
    r.x = lerpf(xy0.x, xy1.x, fx);
    r.y = lerpf(xy0.y, xy1.y, fx);
    r.z = lerpf(zw0.x, zw1.x, fx);
    return r;
}

// Write this voxel's fp16 half into entry i (lo) and entry i-1 (hi).
__device__ __forceinline__ void store_pair16(uint2* __restrict__ b2, int i,
                                             float ox, float oy, float oz) {
    __half2 xy = __floats2half2_rn(ox, oy);
    __half2 zw = __floats2half2_rn(oz, 0.0f);
    uint2 v = make_uint2(*reinterpret_cast<unsigned int*>(&xy),
                         *reinterpret_cast<unsigned int*>(&zw));
    b2[2 * i] = v;                  // entry[i].lo
    if (i > 0) b2[2 * i - 1] = v;   // entry[i-1].hi
}

// Iteration 1 fused with /128 init: trilerp(v/128) == trilerp(v)/128.
__global__ __launch_bounds__(256)
void first_kernel(const float* __restrict__ vel,
                  float* __restrict__ ofx, float* __restrict__ ofy,
                  float* __restrict__ ofz,
                  uint2* __restrict__ out16,
                  const float* __restrict__ rfp) {
    int i = blockIdx.x * blockDim.x + threadIdx.x;
    if (i >= NV) return;

    const float inv = 1.0f / 128.0f;
    const float rf = __ldg(rfp);
    const float sx = rf * 0.5f * (float)(WW - 1) * inv;
    const float sy = rf * 0.5f * (float)(HH - 1) * inv;
    const float sz = rf * 0.5f * (float)(DD - 1) * inv;

    float vx = vel[i], vy = vel[NV + i], vz = vel[2 * NV + i];

    int x = i & (WW - 1);
    int t = i >> 7;
    int y = t % HH;
    int z = t / HH;

    float ix = fminf(fmaxf(fmaf(vx, sx, (float)x), 0.0f), (float)(WW - 1));
    float iy = fminf(fmaxf(fmaf(vy, sy, (float)y), 0.0f), (float)(HH - 1));
    float iz = fminf(fmaxf(fmaf(vz, sz, (float)z), 0.0f), (float)(DD - 1));

    int xb = min((int)ix, WW - 2);  float fx = ix - (float)xb;
    int yb = min((int)iy, HH - 2);  float fy = iy - (float)yb;
    int zb = min((int)iz, DD - 2);  float fz = iz - (float)zb;

    int base = (zb * HH + yb) * WW + xb;
    const int oY = WW, oZ = HH * WW;

    float c[3];
    #pragma unroll
    for (int ch = 0; ch < 3; ch++) {
        const float* p = vel + ch * NV + base;
        float a00 = lerpf(p[0],       p[1],           fx);
        float a01 = lerpf(p[oY],      p[oY + 1],      fx);
        float a10 = lerpf(p[oZ],      p[oZ + 1],      fx);
        float a11 = lerpf(p[oZ + oY], p[oZ + oY + 1], fx);
        c[ch] = lerpf(lerpf(a00, a01, fy), lerpf(a10, a11, fy), fz);
    }

    float ox = (vx + c[0]) * inv;
    float oy = (vy + c[1]) * inv;
    float oz = (vz + c[2]) * inv;

    ofx[i] = ox; ofy[i] = oy; ofz[i] = oz;
    store_pair16(out16, i, ox, oy, oz);
}

template <bool LAST>
__global__ __launch_bounds__(256)
void step_kernel(float* __restrict__ pfx, float* __restrict__ pfy,
                 float* __restrict__ pfz,
                 const uint4* __restrict__ in16,
                 uint2* __restrict__ out16,
                 float* __restrict__ outS,
                 const float* __restrict__ rfp) {
    int i = blockIdx.x * blockDim.x + threadIdx.x;
    if (i >= NV) return;

    const float rf = __ldg(rfp);
    const float sx = rf * 0.5f * (float)(WW - 1);
    const float sy = rf * 0.5f * (float)(HH - 1);
    const float sz = rf * 0.5f * (float)(DD - 1);

    float fX = pfx[i], fY = pfy[i], fZ = pfz[i];

    int x = i & (WW - 1);
    int t = i >> 7;
    int y = t % HH;
    int z = t / HH;

    float ix = fminf(fmaxf(fmaf(fX, sx, (float)x), 0.0f), (float)(WW - 1));
    float iy = fminf(fmaxf(fmaf(fY, sy, (float)y), 0.0f), (float)(HH - 1));
    float iz = fminf(fmaxf(fmaf(fZ, sz, (float)z), 0.0f), (float)(DD - 1));

    int xb = min((int)ix, WW - 2);  float fx = ix - (float)xb;
    int yb = min((int)iy, HH - 2);  float fy = iy - (float)yb;
    int zb = min((int)iz, DD - 2);  float fz = iz - (float)zb;

    int base = (zb * HH + yb) * WW + xb;
    const int oY = WW, oZ = HH * WW;

    float3 c00 = pair_lerp(in16, base,           fx);
    float3 c01 = pair_lerp(in16, base + oY,      fx);
    float3 c10 = pair_lerp(in16, base + oZ,      fx);
    float3 c11 = pair_lerp(in16, base + oZ + oY, fx);

    float cx = lerpf(lerpf(c00.x, c01.x, fy), lerpf(c10.x, c11.x, fy), fz);
    float cy = lerpf(lerpf(c00.y, c01.y, fy), lerpf(c10.y, c11.y, fy), fz);
    float cz = lerpf(lerpf(c00.z, c01.z, fy), lerpf(c10.z, c11.z, fy), fz);

    float ox = fX + cx;
    float oy = fY + cy;
    float oz = fZ + cz;

    if (LAST) {
        outS[i]          = ox;
        outS[NV + i]     = oy;
        outS[2 * NV + i] = oz;
    } else {
        pfx[i] = ox; pfy[i] = oy; pfz[i] = oz;   // in-place fp32 chain
        store_pair16(out16, i, ox, oy, oz);
    }
}

extern "C" void kernel_launch(void* const* d_in, const int* in_sizes, int n_in,
                              void* d_out, int out_size) {
    const float* velocity = (const float*)d_in[0];
    // d_in[1] = sample_grid (identity; folded analytically, unused)
    const float* range_flow = (const float*)d_in[2];
    float* out = (float*)d_out;

    float *fxp, *fyp, *fzp; uint4 *p16A, *p16B;
    cudaGetSymbolAddress((void**)&fxp, g_fx);
    cudaGetSymbolAddress((void**)&fyp, g_fy);
    cudaGetSymbolAddress((void**)&fzp, g_fz);
    cudaGetSymbolAddress((void**)&p16A, g_p16A);
    cudaGetSymbolAddress((void**)&p16B, g_p16B);

    const int threads = 256;
    const int blocks = (NV + threads - 1) / threads;

    // iter 1 (fused with /128 init) -> f32 planes + p16A
    first_kernel<<<blocks, threads>>>(velocity, fxp, fyp, fzp, (uint2*)p16A, range_flow);
    // iters 2..6: fp32 in place, p16 ping-pong
    step_kernel<false><<<blocks, threads>>>(fxp, fyp, fzp, p16A, (uint2*)p16B, nullptr, range_flow);
    step_kernel<false><<<blocks, threads>>>(fxp, fyp, fzp, p16B, (uint2*)p16A, nullptr, range_flow);
    step_kernel<false><<<blocks, threads>>>(fxp, fyp, fzp, p16A, (uint2*)p16B, nullptr, range_flow);
    step_kernel<false><<<blocks, threads>>>(fxp, fyp, fzp, p16B, (uint2*)p16A, nullptr, range_flow);
    step_kernel<false><<<blocks, threads>>>(fxp, fyp, fzp, p16A, (uint2*)p16B, nullptr, range_flow);
    // iter 7: SoA fp32 output
    step_kernel<true ><<<blocks, threads>>>(fxp, fyp, fzp, p16B, nullptr, out, range_flow);
}